// round 16
// baseline (speedup 1.0000x reference)
#include <cuda_runtime.h>
#include <cuda_fp16.h>
#include <cstring>

#define OBS   20
#define PRED  30
#define B_AG  32768
#define ROW2  65536
#define HD    64
#define ED    16
#define KD    80
#define NG    256
#define AB    256               // agents per block
#define NTHR  1024
#define NBLK  (B_AG / AB)       // 128 blocks -> all co-resident
#define KSTR  88                // fp16 row stride (44 words: 16B-aligned + conflict-free)
#define RB    176               // row bytes

// ---- smem byte layout ----
#define SM_W     0               // 256*176 = 45056 (fp16 W, gate-interleaved rows)
#define SM_A     45056           // 45056 (fp16 A tile: x cols 0..15, h cols 16..79)
#define SM_SMALL 90112           // 1280 floats = 5120
#define SM_C     95232           // 256*66*4 = 67584 (c state, [a][jj] stride 66)
#define SM_STAGE 162816          // 256*41*4 = 41984 (phase-1 staging; aliased as sRed)
#define SM_TOTAL 204800
// smalls float offsets
#define O_EMBW 0
#define O_EMBB 640
#define O_LN1G 656
#define O_LN1B 696
#define O_GW   736    // float2[64]: (ln2g*w0, ln2g*w1) per j
#define O_SC   864    // SGW0, SGW1, CB0, CB1
#define O_BIAS 1024   // 256 floats, gate-interleaved (n' = 4j+gate)

// prepped params (c lives in smem; no global state round-trip)
__device__ __align__(16) unsigned short g_W[NG * KSTR];
__device__ __align__(16) float          g_smalls[1280];
__device__ unsigned g_rowcnt[PRED];   // per-out-row completion counters

// ---- helpers ----
__device__ __forceinline__ void cp16(unsigned s, const void* g) {
    asm volatile("cp.async.cg.shared.global [%0], [%1], 16;" :: "r"(s), "l"(g));
}
__device__ __forceinline__ unsigned pkh2(float a, float b) {
    __half2 t = __floats2half2_rn(a, b);
    unsigned u; memcpy(&u, &t, 4); return u;
}
__device__ __forceinline__ float tanhA(float x) {
    float r; asm("tanh.approx.f32 %0, %1;" : "=f"(r) : "f"(x)); return r;
}
__device__ __forceinline__ float sigmA(float x) {
    return fmaf(tanhA(0.5f * x), 0.5f, 0.5f);
}
__device__ __forceinline__ void ldsm4(unsigned& r0, unsigned& r1, unsigned& r2, unsigned& r3,
                                      unsigned addr) {
    asm volatile("ldmatrix.sync.aligned.m8n8.x4.shared.b16 {%0,%1,%2,%3}, [%4];"
                 : "=r"(r0), "=r"(r1), "=r"(r2), "=r"(r3) : "r"(addr));
}
__device__ __forceinline__ void ldsm2(unsigned& r0, unsigned& r1, unsigned addr) {
    asm volatile("ldmatrix.sync.aligned.m8n8.x2.shared.b16 {%0,%1}, [%2];"
                 : "=r"(r0), "=r"(r1) : "r"(addr));
}
__device__ __forceinline__ void mma16816(float& d0, float& d1, float& d2, float& d3,
                                         unsigned a0, unsigned a1, unsigned a2, unsigned a3,
                                         unsigned b0, unsigned b1) {
    asm volatile(
        "mma.sync.aligned.m16n8k16.row.col.f32.f16.f16.f32 "
        "{%0,%1,%2,%3}, {%4,%5,%6,%7}, {%8,%9}, {%0,%1,%2,%3};"
        : "+f"(d0), "+f"(d1), "+f"(d2), "+f"(d3)
        : "r"(a0), "r"(a1), "r"(a2), "r"(a3), "r"(b0), "r"(b1));
}
__device__ __forceinline__ unsigned ldvol(unsigned* p) {
    unsigned v;
    asm volatile("ld.volatile.global.u32 %0, [%1];" : "=r"(v) : "l"(p));
    return v;
}

// ---------------- one-time prep ----------------
__global__ void prep_kernel(const float* __restrict__ W_ih, const float* __restrict__ W_hh,
                            const float* __restrict__ b_ih, const float* __restrict__ b_hh,
                            const float* __restrict__ embW, const float* __restrict__ embB,
                            const float* __restrict__ ln1g, const float* __restrict__ ln1b,
                            const float* __restrict__ ln2g, const float* __restrict__ ln2b,
                            const float* __restrict__ h2pW, const float* __restrict__ h2pB)
{
    const int gid = blockIdx.x * blockDim.x + threadIdx.x;
    if (gid < PRED) g_rowcnt[gid] = 0;
    if (gid < NG * KD) {
        const int np = gid / KD;
        const int k  = gid % KD;
        const int n  = (np & 3) * HD + (np >> 2);   // gate-interleaved rows
        float w = (k < ED) ? W_ih[n * ED + k] : W_hh[n * HD + (k - ED)];
        __half h = __float2half(w);
        unsigned short hs; memcpy(&hs, &h, 2);
        g_W[np * KSTR + k] = hs;
    }
    if (gid < 1280) {
        float v;
        if (gid < 640)       v = embW[gid];
        else if (gid < 656)  v = embB[gid - 640];
        else if (gid < 696)  v = ln1g[gid - 656];
        else if (gid < 736)  v = ln1b[gid - 696];
        else if (gid < 864) {                       // gw pairs
            int q = gid - 736;
            int j = q >> 1;
            v = ln2g[j] * h2pW[(q & 1) * 64 + j];
        }
        else if (gid < 868) {                       // scalars
            int w = gid - 864;
            float acc = 0.f;
            if (w < 2) { for (int j = 0; j < 64; j++) acc += ln2g[j] * h2pW[w * 64 + j]; }
            else {
                int o = w - 2;
                for (int j = 0; j < 64; j++) acc += ln2b[j] * h2pW[o * 64 + j];
                acc += h2pB[o];
            }
            v = acc;
        }
        else if (gid >= 1024) {
            int np = gid - 1024;
            int n  = (np & 3) * HD + (np >> 2);
            v = b_ih[n] + b_hh[n];
        }
        else                 v = 0.f;
        g_smalls[gid] = v;
    }
}

// ---------------- persistent kernel: all 30 steps, 1024 threads ----------------
__global__ void __launch_bounds__(NTHR, 1)
lstm_persist(const float* __restrict__ trajAbs,
             const float* __restrict__ decoderH,
             float* __restrict__ out)
{
    extern __shared__ char sm[];
    float* sSm    = (float*)(sm + SM_SMALL);
    float* sBias  = sSm + O_BIAS;
    float* sC     = (float*)(sm + SM_C);
    float* sStage = (float*)(sm + SM_STAGE);
    float* sRed   = sStage;                 // alias: 2*256*4 floats after phase 1

    const int tid  = threadIdx.x;
    const int lane = tid & 31;
    const int wid  = tid >> 5;
    const int b0   = blockIdx.x * AB;
    const unsigned sb = (unsigned)__cvta_generic_to_shared(sm);
    const int tmax_blk = (10240 * blockIdx.x + 10239) >> 16;

    // ---- one-time: W tile (44 KB), smalls, zero c, initial h -> A cols 16..79 ----
    {
#pragma unroll
        for (int i = 0; i < 3; i++) {
            int c = tid + i * NTHR;
            if (c < 2816) cp16(sb + SM_W + c * 16, (const char*)g_W + c * 16);
        }
        asm volatile("cp.async.commit_group;");
    }
    if (tid < 320) ((float4*)sSm)[tid] = ((const float4*)g_smalls)[tid];
#pragma unroll
    for (int i = 0; i < 17; i++) {
        int c = tid + i * NTHR;
        if (c < 16896) sC[c] = 0.f;
    }
    {
#pragma unroll
        for (int it = 0; it < 4; it++) {
            int idx = tid + it * NTHR;       // 4096 float4s
            int a = idx >> 4;
            int j = (idx & 15) * 4;
            float4 hv = *(const float4*)(decoderH + (b0 + a) * HD + j);
            unsigned off = a * RB + (16 + j) * 2;
            *(unsigned*)(sm + SM_A + off)     = pkh2(hv.x, hv.y);
            *(unsigned*)(sm + SM_A + off + 4) = pkh2(hv.z, hv.w);
        }
    }
    asm volatile("cp.async.wait_group 0;");
    __syncthreads();

    // invariant lane/warp constants
    const int g    = lane >> 2;
    const int tig  = lane & 3;
    const int oddp = tig & 1;
    const int pr   = wid & 15;       // m-tile (16 rows of agents)
    const int hf   = wid >> 4;       // nt half (0: nt 0..15, 1: nt 16..31)
    const int jj_base = tig >> 1;
    const int a_loc = pr * 16 + g + (oddp ? 8 : 0);
    const unsigned abase = (pr * 16 + ((lane >> 3) & 1) * 8 + (lane & 7)) * RB
                         + (lane >> 4) * 16;
    const unsigned brow4_0 = sb + SM_W + (lane & 7) * RB + (lane >> 3) * 16;
    const unsigned brow2_0 = sb + SM_W + (lane & 7) * RB + 128 + ((lane >> 3) & 1) * 16;
    const int nt0 = hf * 16;

    for (int s = 0; s < PRED; s++) {
        // ---------------- wait for the freshest out row this step needs ----------
        {
            const int r_need = s + tmax_blk - 20;
            if (r_need >= 0) {
                if (tid == 0) {
                    while (ldvol(&g_rowcnt[r_need]) < (unsigned)NBLK) __nanosleep(32);
                    __threadfence();
                }
                __syncthreads();
            }
        }

        // ---------------- phase 1a: coalesced gather -> staging smem -------------
        {
            const int base = s * ROW2 + b0 * 40;
#pragma unroll
            for (int i = 0; i < 10; i++) {
                int idx  = tid + i * NTHR;          // 0..10239
                int gidx = base + idx;
                float v = (gidx < OBS * ROW2) ? trajAbs[gidx]
                                              : out[gidx - OBS * ROW2];
                sStage[(idx / 40) * 41 + (idx % 40)] = v;
            }
        }
        __syncthreads();

        // ---------------- phase 1b: LN1 + embed + leaky -> A cols 0..15 ----------
        {
            const int a  = tid >> 2;
            const int jt = tid & 3;
            float raw[10];
            const float* sp = sStage + a * 41 + jt * 10;
#pragma unroll
            for (int u = 0; u < 10; u++) raw[u] = sp[u];

            float sum = 0.f, sq = 0.f;
#pragma unroll
            for (int u = 0; u < 10; u++) { sum += raw[u]; sq += raw[u] * raw[u]; }
            sum += __shfl_xor_sync(0xffffffffu, sum, 1);
            sum += __shfl_xor_sync(0xffffffffu, sum, 2);
            sq  += __shfl_xor_sync(0xffffffffu, sq, 1);
            sq  += __shfl_xor_sync(0xffffffffu, sq, 2);
            const float mean = sum * 0.025f;
            const float var  = sq * 0.025f - mean * mean;
            const float rstd = rsqrtf(var + 1e-5f);

            float xn[10];
#pragma unroll
            for (int u = 0; u < 10; u++) {
                int idx = jt * 10 + u;
                xn[u] = (raw[u] - mean) * rstd * sSm[O_LN1G + idx] + sSm[O_LN1B + idx];
            }
            float p[16];
#pragma unroll
            for (int e = 0; e < 16; e++) {
                const float* wrow = sSm + O_EMBW + e * 40 + jt * 10;
                float acc = 0.f;
#pragma unroll
                for (int u = 0; u < 10; u++) acc = fmaf(xn[u], wrow[u], acc);
                acc += __shfl_xor_sync(0xffffffffu, acc, 1);
                acc += __shfl_xor_sync(0xffffffffu, acc, 2);
                p[e] = acc;
            }
#pragma unroll
            for (int i = 0; i < 2; i++) {
                int e = jt * 4 + 2 * i;
                float v0 = p[e]   + sSm[O_EMBB + e];
                float v1 = p[e+1] + sSm[O_EMBB + e + 1];
                v0 = v0 > 0.f ? v0 : 0.01f * v0;
                v1 = v1 > 0.f ? v1 : 0.01f * v1;
                *(unsigned*)(sm + SM_A + a * RB + e * 2) = pkh2(v0, v1);
            }
        }
        __syncthreads();

        // ---------------- A-fragment preload (1 m-tile per warp) -----------------
        unsigned af[5][4];
#pragma unroll
        for (int kt = 0; kt < 5; kt++)
            ldsm4(af[kt][0], af[kt][1], af[kt][2], af[kt][3],
                  sb + SM_A + abase + kt * 32);
        __syncthreads();   // A reads done; h-writes below are for next step

        // ---------------- GEMM + fused LSTM cell (half nt range, 1 m-tile) -------
        float sum_h = 0.f, sq_h = 0.f, S0 = 0.f, S1 = 0.f;

#pragma unroll 1
        for (int nt = nt0; nt < nt0 + 16; nt++) {
            unsigned bq[10];
            {
                unsigned r4 = brow4_0 + nt * (8 * RB);
                ldsm4(bq[0], bq[1], bq[2], bq[3], r4);
                ldsm4(bq[4], bq[5], bq[6], bq[7], r4 + 64);
                ldsm2(bq[8], bq[9], brow2_0 + nt * (8 * RB));
            }
            const int jj = 2 * nt + jj_base;
            float4 bias = *(const float4*)(sBias + 4 * jj);
            float2 gw = *(const float2*)(sSm + O_GW + 2 * jj);

            float c_old = sC[a_loc * 66 + jj];
            float d0 = 0.f, d1 = 0.f, d2 = 0.f, d3 = 0.f;
#pragma unroll
            for (int kt = 0; kt < 5; kt++)
                mma16816(d0, d1, d2, d3, af[kt][0], af[kt][1], af[kt][2], af[kt][3],
                         bq[2*kt], bq[2*kt+1]);
            float r0 = __shfl_xor_sync(0xffffffffu, d0, 1);
            float r1 = __shfl_xor_sync(0xffffffffu, d1, 1);
            float r2 = __shfl_xor_sync(0xffffffffu, d2, 1);
            float r3 = __shfl_xor_sync(0xffffffffu, d3, 1);
            float iv = (oddp ? r2 : d0) + bias.x;
            float fv = (oddp ? r3 : d1) + bias.y;
            float gv = (oddp ? d2 : r0) + bias.z;
            float ov = (oddp ? d3 : r1) + bias.w;

            float ig = sigmA(iv);
            float fg = sigmA(fv);
            float og = sigmA(ov);
            float gg = tanhA(gv);
            float c2 = fmaf(fg, c_old, ig * gg);
            float hv = og * tanhA(c2);
            sC[a_loc * 66 + jj] = c2;
            *(__half*)(sm + SM_A + a_loc * RB + (16 + jj) * 2) = __float2half(hv);

            sum_h += hv;
            sq_h   = fmaf(hv, hv, sq_h);
            S0 = fmaf(hv, gw.x, S0);
            S1 = fmaf(hv, gw.y, S1);
        }

        // combine jj-parities within warp, then cross-warp via smem
        sum_h += __shfl_xor_sync(0xffffffffu, sum_h, 2);
        sq_h  += __shfl_xor_sync(0xffffffffu, sq_h, 2);
        S0    += __shfl_xor_sync(0xffffffffu, S0, 2);
        S1    += __shfl_xor_sync(0xffffffffu, S1, 2);
        if (tig < 2) {
            int a = pr * 16 + g + 8 * tig;
            *(float4*)(sRed + (hf * 256 + a) * 4) =
                make_float4(sum_h, sq_h, S0, S1);
        }
        __syncthreads();

        if (tid < 256) {
            float4 u = *(const float4*)(sRed + tid * 4);
            float4 v = *(const float4*)(sRed + (256 + tid) * 4);
            const float sum = u.x + v.x, sq = u.y + v.y;
            const float s0 = u.z + v.z, s1 = u.w + v.w;
            const float m    = sum * 0.015625f;
            const float var  = sq * 0.015625f - m * m;
            const float rstd = rsqrtf(var + 1e-5f);
            float2 r = make_float2(rstd * (s0 - m * sSm[O_SC + 0]) + sSm[O_SC + 2],
                                   rstd * (s1 - m * sSm[O_SC + 1]) + sSm[O_SC + 3]);
            *(float2*)(out + s * ROW2 + (b0 + tid) * 2) = r;
        }

        // ---------------- publish row s ------------------------------------------
        if (s < PRED - 1) {
            __threadfence();
            __syncthreads();
            if (tid == 0) atomicAdd(&g_rowcnt[s], 1u);
        }
    }
}

extern "C" void kernel_launch(void* const* d_in, const int* in_sizes, int n_in,
                              void* d_out, int out_size)
{
    const float* trajAbs  = (const float*)d_in[0];
    const float* decoderH = (const float*)d_in[2];
    const float* W_ih = (const float*)d_in[3];
    const float* W_hh = (const float*)d_in[4];
    const float* b_ih = (const float*)d_in[5];
    const float* b_hh = (const float*)d_in[6];
    const float* embW = (const float*)d_in[7];
    const float* embB = (const float*)d_in[8];
    const float* h2pW = (const float*)d_in[9];
    const float* h2pB = (const float*)d_in[10];
    const float* ln1g = (const float*)d_in[11];
    const float* ln1b = (const float*)d_in[12];
    const float* ln2g = (const float*)d_in[13];
    const float* ln2b = (const float*)d_in[14];
    float* out = (float*)d_out;

    prep_kernel<<<80, 256>>>(
        W_ih, W_hh, b_ih, b_hh, embW, embB,
        ln1g, ln1b, ln2g, ln2b, h2pW, h2pB);

    cudaFuncSetAttribute(lstm_persist, cudaFuncAttributeMaxDynamicSharedMemorySize,
                         SM_TOTAL);

    lstm_persist<<<NBLK, NTHR, SM_TOTAL>>>(trajAbs, decoderH, out);
}

// round 17
// speedup vs baseline: 1.2741x; 1.2741x over previous
#include <cuda_runtime.h>
#include <cuda_fp16.h>
#include <cstring>

#define OBS   20
#define PRED  30
#define B_AG  32768
#define ROW2  65536
#define HD    64
#define ED    16
#define KD    80
#define NG    256
#define AB    256               // agents per block
#define NTHR  512
#define NBLK  (B_AG / AB)       // 128 blocks -> all co-resident (148 SMs)
#define KSTR  88                // fp16 row stride (44 words: 16B-aligned + conflict-free)
#define RB    176               // row bytes

// ---- smem byte layout (c-state now lives in registers) ----
#define SM_W     0               // 256*176 = 45056 (fp16 W, gate-interleaved rows)
#define SM_A     45056           // 45056 (fp16 A tile: x cols 0..15, h cols 16..79)
#define SM_SMALL 90112           // 1280 floats = 5120
#define SM_STAGE 95232           // 256*41*4 = 41984 (phase-1 staging; aliased as sRed)
#define SM_TOTAL 137216
// smalls float offsets
#define O_EMBW 0
#define O_EMBB 640
#define O_LN1G 656
#define O_LN1B 696
#define O_GW   736    // float2[64]: (ln2g*w0, ln2g*w1) per j
#define O_SC   864    // SGW0, SGW1, CB0, CB1
#define O_BIAS 1024   // 256 floats, gate-interleaved (n' = 4j+gate)

// prepped params
__device__ __align__(16) unsigned short g_W[NG * KSTR];
__device__ __align__(16) float          g_smalls[1280];
__device__ unsigned g_rowcnt[PRED];   // per-out-row completion counters

// ---- helpers ----
__device__ __forceinline__ void cp16(unsigned s, const void* g) {
    asm volatile("cp.async.cg.shared.global [%0], [%1], 16;" :: "r"(s), "l"(g));
}
__device__ __forceinline__ unsigned pkh2(float a, float b) {
    __half2 t = __floats2half2_rn(a, b);
    unsigned u; memcpy(&u, &t, 4); return u;
}
__device__ __forceinline__ float tanhA(float x) {
    float r; asm("tanh.approx.f32 %0, %1;" : "=f"(r) : "f"(x)); return r;
}
__device__ __forceinline__ float sigmA(float x) {
    return fmaf(tanhA(0.5f * x), 0.5f, 0.5f);
}
__device__ __forceinline__ void ldsm4(unsigned& r0, unsigned& r1, unsigned& r2, unsigned& r3,
                                      unsigned addr) {
    asm volatile("ldmatrix.sync.aligned.m8n8.x4.shared.b16 {%0,%1,%2,%3}, [%4];"
                 : "=r"(r0), "=r"(r1), "=r"(r2), "=r"(r3) : "r"(addr));
}
__device__ __forceinline__ void ldsm2(unsigned& r0, unsigned& r1, unsigned addr) {
    asm volatile("ldmatrix.sync.aligned.m8n8.x2.shared.b16 {%0,%1}, [%2];"
                 : "=r"(r0), "=r"(r1) : "r"(addr));
}
__device__ __forceinline__ void mma16816(float& d0, float& d1, float& d2, float& d3,
                                         unsigned a0, unsigned a1, unsigned a2, unsigned a3,
                                         unsigned b0, unsigned b1) {
    asm volatile(
        "mma.sync.aligned.m16n8k16.row.col.f32.f16.f16.f32 "
        "{%0,%1,%2,%3}, {%4,%5,%6,%7}, {%8,%9}, {%0,%1,%2,%3};"
        : "+f"(d0), "+f"(d1), "+f"(d2), "+f"(d3)
        : "r"(a0), "r"(a1), "r"(a2), "r"(a3), "r"(b0), "r"(b1));
}
__device__ __forceinline__ unsigned ldvol(unsigned* p) {
    unsigned v;
    asm volatile("ld.volatile.global.u32 %0, [%1];" : "=r"(v) : "l"(p));
    return v;
}

// ---------------- one-time prep ----------------
__global__ void prep_kernel(const float* __restrict__ W_ih, const float* __restrict__ W_hh,
                            const float* __restrict__ b_ih, const float* __restrict__ b_hh,
                            const float* __restrict__ embW, const float* __restrict__ embB,
                            const float* __restrict__ ln1g, const float* __restrict__ ln1b,
                            const float* __restrict__ ln2g, const float* __restrict__ ln2b,
                            const float* __restrict__ h2pW, const float* __restrict__ h2pB)
{
    const int gid = blockIdx.x * blockDim.x + threadIdx.x;
    if (gid < PRED) g_rowcnt[gid] = 0;
    if (gid < NG * KD) {
        const int np = gid / KD;
        const int k  = gid % KD;
        const int n  = (np & 3) * HD + (np >> 2);   // gate-interleaved rows
        float w = (k < ED) ? W_ih[n * ED + k] : W_hh[n * HD + (k - ED)];
        __half h = __float2half(w);
        unsigned short hs; memcpy(&hs, &h, 2);
        g_W[np * KSTR + k] = hs;
    }
    if (gid < 1280) {
        float v;
        if (gid < 640)       v = embW[gid];
        else if (gid < 656)  v = embB[gid - 640];
        else if (gid < 696)  v = ln1g[gid - 656];
        else if (gid < 736)  v = ln1b[gid - 696];
        else if (gid < 864) {                       // gw pairs
            int q = gid - 736;
            int j = q >> 1;
            v = ln2g[j] * h2pW[(q & 1) * 64 + j];
        }
        else if (gid < 868) {                       // scalars
            int w = gid - 864;
            float acc = 0.f;
            if (w < 2) { for (int j = 0; j < 64; j++) acc += ln2g[j] * h2pW[w * 64 + j]; }
            else {
                int o = w - 2;
                for (int j = 0; j < 64; j++) acc += ln2b[j] * h2pW[o * 64 + j];
                acc += h2pB[o];
            }
            v = acc;
        }
        else if (gid >= 1024) {
            int np = gid - 1024;
            int n  = (np & 3) * HD + (np >> 2);
            v = b_ih[n] + b_hh[n];
        }
        else                 v = 0.f;
        g_smalls[gid] = v;
    }
}

// ---------------- persistent kernel: all 30 steps, c in registers --------------
__global__ void __launch_bounds__(NTHR, 1)
lstm_persist(const float* __restrict__ trajAbs,
             const float* __restrict__ decoderH,
             float* __restrict__ out)
{
    extern __shared__ char sm[];
    float* sSm    = (float*)(sm + SM_SMALL);
    float* sBias  = sSm + O_BIAS;
    float* sStage = (float*)(sm + SM_STAGE);
    float* sRed   = sStage;                 // alias: 2*256*4 floats after phase 1

    const int tid  = threadIdx.x;
    const int lane = tid & 31;
    const int wid  = tid >> 5;
    const int b0   = blockIdx.x * AB;
    const unsigned sb = (unsigned)__cvta_generic_to_shared(sm);
    const int tmax_blk = (10240 * blockIdx.x + 10239) >> 16;

    // ---- one-time: W tile (44 KB), smalls, initial h -> A cols 16..79 ----
    {
#pragma unroll
        for (int i = 0; i < 6; i++) {
            int c = tid + i * NTHR;
            if (c < 2816) cp16(sb + SM_W + c * 16, (const char*)g_W + c * 16);
        }
        asm volatile("cp.async.commit_group;");
    }
    if (tid < 320) ((float4*)sSm)[tid] = ((const float4*)g_smalls)[tid];
    {
#pragma unroll
        for (int it = 0; it < 8; it++) {
            int idx = tid + it * NTHR;       // 4096 float4s
            int a = idx >> 4;
            int j = (idx & 15) * 4;
            float4 hv = *(const float4*)(decoderH + (b0 + a) * HD + j);
            unsigned off = a * RB + (16 + j) * 2;
            *(unsigned*)(sm + SM_A + off)     = pkh2(hv.x, hv.y);
            *(unsigned*)(sm + SM_A + off + 4) = pkh2(hv.z, hv.w);
        }
    }
    asm volatile("cp.async.wait_group 0;");
    __syncthreads();

    // invariant lane/warp constants
    const int g    = lane >> 2;
    const int tig  = lane & 3;
    const int oddp = tig & 1;
    const int pr   = wid & 7;        // m-tile pair index
    const int hf   = wid >> 3;       // nt half (0: nt 0..15, 1: nt 16..31)
    const int jj_base = tig >> 1;
    int a_loc[2];
    a_loc[0] = (2 * pr) * 16 + g + (oddp ? 8 : 0);
    a_loc[1] = (2 * pr + 1) * 16 + g + (oddp ? 8 : 0);
    unsigned abase[2];
#pragma unroll
    for (int m = 0; m < 2; m++)
        abase[m] = ((2 * pr + m) * 16 + ((lane >> 3) & 1) * 8 + (lane & 7)) * RB
                 + (lane >> 4) * 16;
    const unsigned brow4_0 = sb + SM_W + (lane & 7) * RB + (lane >> 3) * 16;
    const unsigned brow2_0 = sb + SM_W + (lane & 7) * RB + 128 + ((lane >> 3) & 1) * 16;
    const int nt0 = hf * 16;

    // c state lives entirely in registers: lane owns cells (jj = 2(nt0+i)+jj_base,
    // a_loc[m]) for i in 0..15, m in 0..1 — the same cells every step.
    float cReg[2][16];
#pragma unroll
    for (int m = 0; m < 2; m++)
#pragma unroll
        for (int i = 0; i < 16; i++) cReg[m][i] = 0.f;

    for (int s = 0; s < PRED; s++) {
        // ---------------- wait for the freshest out row this step needs ----------
        {
            const int r_need = s + tmax_blk - 20;
            if (r_need >= 0) {
                if (tid == 0) {
                    while (ldvol(&g_rowcnt[r_need]) < (unsigned)NBLK) __nanosleep(32);
                    __threadfence();
                }
                __syncthreads();
            }
        }

        // ---------------- phase 1a: coalesced gather -> staging smem -------------
        {
            const int base = s * ROW2 + b0 * 40;
#pragma unroll
            for (int i = 0; i < 20; i++) {
                int idx  = tid + i * NTHR;          // 0..10239
                int gidx = base + idx;
                float v = (gidx < OBS * ROW2) ? trajAbs[gidx]
                                              : out[gidx - OBS * ROW2];
                sStage[(idx / 40) * 41 + (idx % 40)] = v;
            }
        }
        __syncthreads();

        // ---------------- phase 1b: LN1 + embed + leaky -> A cols 0..15 ----------
        {
            const int a  = tid >> 1;
            const int jt = tid & 1;
            float raw[20];
            const float* sp = sStage + a * 41 + jt * 20;
#pragma unroll
            for (int u = 0; u < 20; u++) raw[u] = sp[u];

            float sum = 0.f, sq = 0.f;
#pragma unroll
            for (int u = 0; u < 20; u++) { sum += raw[u]; sq += raw[u] * raw[u]; }
            sum += __shfl_xor_sync(0xffffffffu, sum, 1);
            sq  += __shfl_xor_sync(0xffffffffu, sq, 1);
            const float mean = sum * 0.025f;
            const float var  = sq * 0.025f - mean * mean;
            const float rstd = rsqrtf(var + 1e-5f);

            float xn[20];
#pragma unroll
            for (int u = 0; u < 20; u++) {
                int idx = jt * 20 + u;
                xn[u] = (raw[u] - mean) * rstd * sSm[O_LN1G + idx] + sSm[O_LN1B + idx];
            }
            float p[16];
#pragma unroll
            for (int e = 0; e < 16; e++) {
                const float* wrow = sSm + O_EMBW + e * 40 + jt * 20;
                float acc = 0.f;
#pragma unroll
                for (int q = 0; q < 5; q++) {
                    float4 w = *(const float4*)(wrow + 4 * q);
                    acc = fmaf(xn[4*q],   w.x, acc);
                    acc = fmaf(xn[4*q+1], w.y, acc);
                    acc = fmaf(xn[4*q+2], w.z, acc);
                    acc = fmaf(xn[4*q+3], w.w, acc);
                }
                p[e] = acc + __shfl_xor_sync(0xffffffffu, acc, 1);
            }
#pragma unroll
            for (int i = 0; i < 4; i++) {
                int e = jt * 8 + 2 * i;
                float v0 = p[e]   + sSm[O_EMBB + e];
                float v1 = p[e+1] + sSm[O_EMBB + e + 1];
                v0 = v0 > 0.f ? v0 : 0.01f * v0;
                v1 = v1 > 0.f ? v1 : 0.01f * v1;
                *(unsigned*)(sm + SM_A + a * RB + e * 2) = pkh2(v0, v1);
            }
        }
        __syncthreads();

        // ---------------- A-fragment preload (2 m-tiles per warp) ----------------
        unsigned af[2][5][4];
#pragma unroll
        for (int m = 0; m < 2; m++)
#pragma unroll
            for (int kt = 0; kt < 5; kt++)
                ldsm4(af[m][kt][0], af[m][kt][1], af[m][kt][2], af[m][kt][3],
                      sb + SM_A + abase[m] + kt * 32);
        __syncthreads();   // A reads done; h-writes below are for next step

        // ---------------- GEMM + fused LSTM cell (c in registers) ----------------
        float sum_h[2] = {0.f, 0.f}, sq_h[2] = {0.f, 0.f};
        float S0[2] = {0.f, 0.f}, S1[2] = {0.f, 0.f};

#pragma unroll 1
        for (int i = 0; i < 16; i++) {
            const int nt = nt0 + i;
            unsigned bq[10];
            {
                unsigned r4 = brow4_0 + nt * (8 * RB);
                ldsm4(bq[0], bq[1], bq[2], bq[3], r4);
                ldsm4(bq[4], bq[5], bq[6], bq[7], r4 + 64);
                ldsm2(bq[8], bq[9], brow2_0 + nt * (8 * RB));
            }
            const int jj = 2 * nt + jj_base;
            float4 bias = *(const float4*)(sBias + 4 * jj);
            float2 gw = *(const float2*)(sSm + O_GW + 2 * jj);
#pragma unroll
            for (int m = 0; m < 2; m++) {
                float d0 = 0.f, d1 = 0.f, d2 = 0.f, d3 = 0.f;
#pragma unroll
                for (int kt = 0; kt < 5; kt++)
                    mma16816(d0, d1, d2, d3,
                             af[m][kt][0], af[m][kt][1], af[m][kt][2], af[m][kt][3],
                             bq[2*kt], bq[2*kt+1]);
                float r0 = __shfl_xor_sync(0xffffffffu, d0, 1);
                float r1 = __shfl_xor_sync(0xffffffffu, d1, 1);
                float r2 = __shfl_xor_sync(0xffffffffu, d2, 1);
                float r3 = __shfl_xor_sync(0xffffffffu, d3, 1);
                float iv = (oddp ? r2 : d0) + bias.x;
                float fv = (oddp ? r3 : d1) + bias.y;
                float gv = (oddp ? d2 : r0) + bias.z;
                float ov = (oddp ? d3 : r1) + bias.w;

                float ig = sigmA(iv);
                float fg = sigmA(fv);
                float og = sigmA(ov);
                float gg = tanhA(gv);
                float c2 = fmaf(fg, cReg[m][i], ig * gg);
                float hv = og * tanhA(c2);
                cReg[m][i] = c2;
                *(__half*)(sm + SM_A + a_loc[m] * RB + (16 + jj) * 2) = __float2half(hv);

                sum_h[m] += hv;
                sq_h[m]   = fmaf(hv, hv, sq_h[m]);
                S0[m] = fmaf(hv, gw.x, S0[m]);
                S1[m] = fmaf(hv, gw.y, S1[m]);
            }
        }

        // combine jj-parities within warp, then cross-warp via smem
#pragma unroll
        for (int m = 0; m < 2; m++) {
            sum_h[m] += __shfl_xor_sync(0xffffffffu, sum_h[m], 2);
            sq_h[m]  += __shfl_xor_sync(0xffffffffu, sq_h[m], 2);
            S0[m]    += __shfl_xor_sync(0xffffffffu, S0[m], 2);
            S1[m]    += __shfl_xor_sync(0xffffffffu, S1[m], 2);
        }
        if (tig < 2) {
#pragma unroll
            for (int m = 0; m < 2; m++) {
                int a = (2 * pr + m) * 16 + g + 8 * tig;
                *(float4*)(sRed + (hf * 256 + a) * 4) =
                    make_float4(sum_h[m], sq_h[m], S0[m], S1[m]);
            }
        }
        __syncthreads();

        if (tid < 256) {
            float4 u = *(const float4*)(sRed + tid * 4);
            float4 v = *(const float4*)(sRed + (256 + tid) * 4);
            const float sum = u.x + v.x, sq = u.y + v.y;
            const float s0 = u.z + v.z, s1 = u.w + v.w;
            const float m    = sum * 0.015625f;
            const float var  = sq * 0.015625f - m * m;
            const float rstd = rsqrtf(var + 1e-5f);
            float2 r = make_float2(rstd * (s0 - m * sSm[O_SC + 0]) + sSm[O_SC + 2],
                                   rstd * (s1 - m * sSm[O_SC + 1]) + sSm[O_SC + 3]);
            *(float2*)(out + s * ROW2 + (b0 + tid) * 2) = r;
        }

        // ---------------- publish row s ------------------------------------------
        if (s < PRED - 1) {
            __threadfence();
            __syncthreads();
            if (tid == 0) atomicAdd(&g_rowcnt[s], 1u);
        }
    }
}

extern "C" void kernel_launch(void* const* d_in, const int* in_sizes, int n_in,
                              void* d_out, int out_size)
{
    const float* trajAbs  = (const float*)d_in[0];
    const float* decoderH = (const float*)d_in[2];
    const float* W_ih = (const float*)d_in[3];
    const float* W_hh = (const float*)d_in[4];
    const float* b_ih = (const float*)d_in[5];
    const float* b_hh = (const float*)d_in[6];
    const float* embW = (const float*)d_in[7];
    const float* embB = (const float*)d_in[8];
    const float* h2pW = (const float*)d_in[9];
    const float* h2pB = (const float*)d_in[10];
    const float* ln1g = (const float*)d_in[11];
    const float* ln1b = (const float*)d_in[12];
    const float* ln2g = (const float*)d_in[13];
    const float* ln2b = (const float*)d_in[14];
    float* out = (float*)d_out;

    prep_kernel<<<80, 256>>>(
        W_ih, W_hh, b_ih, b_hh, embW, embB,
        ln1g, ln1b, ln2g, ln2b, h2pW, h2pB);

    cudaFuncSetAttribute(lstm_persist, cudaFuncAttributeMaxDynamicSharedMemorySize,
                         SM_TOTAL);

    lstm_persist<<<NBLK, NTHR, SM_TOTAL>>>(trajAbs, decoderH, out);
}